// round 4
// baseline (speedup 1.0000x reference)
#include <cuda_runtime.h>
#include <cuda_fp16.h>
#include <stdint.h>

// Problem constants
#define BB   32
#define CC   256
#define HIN  30
#define OH   28
#define PPB  784
#define NPIX 25088
#define NK   2048
#define BOWOFF (BB*NK)

// Pass-1 tiling
#define BM 128               // pixels per block
#define BN 256               // codes per tile
#define NTILE (NK/BN)        // 8
#define NSTAGE (NTILE*8)     // 64 stages: per tile 4 k-chunks x {hi,lo}
#define NBLK (NPIX/BM)       // 196
#define ASTR 272             // A smem row stride (halves), conflict-free
#define BSTR 80              // B smem row stride (halves), conflict-free
#define CHUNK_HALVES (BN*BSTR)        // 20480
#define CHUNK_BYTES  (CHUNK_HALVES*2) // 40960

// smem byte offsets
#define OFF_AH 0
#define OFF_AL 69632
#define OFF_B  139264
#define OFF_E2 221184
#define OFF_F2 222208
#define OFF_MR 222720
#define OFF_SR 223232
#define OFF_MP 223744
#define OFF_SP 225792
#define OFF_MN 227840
#define SMEM_BYTES 228352

// Scratch
__device__ float g_e2[NK];
__device__ float g_bowp[2][NBLK][NK];
__device__ __align__(16) __half g_ehiP[NK*CC];  // k-permuted fp16 hi split
__device__ __align__(16) __half g_eloP[NK*CC];  // k-permuted fp16 lo split

// ---------------------------------------------------------------------------
__device__ __forceinline__ void mma16816(float* c, const unsigned* a,
                                         unsigned b0, unsigned b1) {
    asm volatile(
        "mma.sync.aligned.m16n8k16.row.col.f32.f16.f16.f32 "
        "{%0,%1,%2,%3}, {%4,%5,%6,%7}, {%8,%9}, {%0,%1,%2,%3};"
        : "+f"(c[0]), "+f"(c[1]), "+f"(c[2]), "+f"(c[3])
        : "r"(a[0]), "r"(a[1]), "r"(a[2]), "r"(a[3]), "r"(b0), "r"(b1));
}

// ---------------------------------------------------------------------------
// Pass 0a: e2[k]
// ---------------------------------------------------------------------------
__global__ void e2_kernel(const float* __restrict__ emb) {
    int gw = blockIdx.x * (blockDim.x >> 5) + (threadIdx.x >> 5);
    int lane = threadIdx.x & 31;
    if (gw >= NK) return;
    const float4* row = reinterpret_cast<const float4*>(emb + (size_t)gw * CC);
    float s = 0.f;
    #pragma unroll
    for (int i = lane; i < CC/4; i += 32) {
        float4 v = row[i];
        s += v.x*v.x + v.y*v.y + v.z*v.z + v.w*v.w;
    }
    #pragma unroll
    for (int o = 16; o; o >>= 1) s += __shfl_xor_sync(0xffffffffu, s, o);
    if (lane == 0) g_e2[gw] = s;
}

// ---------------------------------------------------------------------------
// Pass 0b: fp16 hi/lo split of embedding, k-permuted fragment layout
// ---------------------------------------------------------------------------
__global__ void split_kernel(const float* __restrict__ emb) {
    int idx = blockIdx.x * 256 + threadIdx.x;
    if (idx >= NK*(CC/2)) return;
    int k  = idx >> 7;
    int cp = idx & 127;
    float v0 = emb[k*CC + 2*cp];
    float v1 = emb[k*CC + 2*cp + 1];
    __half h0 = __float2half_rn(v0), h1 = __float2half_rn(v1);
    __half l0 = __float2half_rn(v0 - __half2float(h0));
    __half l1 = __float2half_rn(v1 - __half2float(h1));
    int jp = cp & 7, grp = cp >> 3;
    int phys = grp*16 + (((jp & 3) << 1) + (jp >> 2)) * 2;
    *(__half2*)&g_ehiP[(size_t)k*CC + phys] = __halves2half2(h0, h1);
    *(__half2*)&g_eloP[(size_t)k*CC + phys] = __halves2half2(l0, l1);
}

// ---------------------------------------------------------------------------
// Pass 1: fp16-split HMMA GEMM (BM=128 x all 2048 codes) + online softmax
//         + raw logit store + fused in-kernel softmax fix-up & bow partials.
// 8 warps as 2m x 4n; warp tile 64x64; acc fp32 [4][8][4].
// ---------------------------------------------------------------------------
extern __shared__ char smem_raw[];

__global__ __launch_bounds__(256, 1)
void pass1_kernel(const float* __restrict__ feat,
                  const float* __restrict__ md,
                  float* __restrict__ out)
{
    __half* Ah   = (__half*)(smem_raw + OFF_AH);  // [128][272]
    __half* Al   = (__half*)(smem_raw + OFF_AL);  // [128][272]
    __half* Bbuf = (__half*)(smem_raw + OFF_B);   // 2 x [256][80]
    float* e2s   = (float*)(smem_raw + OFF_E2);   // 256
    float* f2s   = (float*)(smem_raw + OFF_F2);   // 128
    float* m_run = (float*)(smem_raw + OFF_MR);   // 128
    float* s_run = (float*)(smem_raw + OFF_SR);   // 128
    float* mpart = (float*)(smem_raw + OFF_MP);   // 4 x 128
    float* spart = (float*)(smem_raw + OFF_SP);   // 4 x 128
    float* mnew  = (float*)(smem_raw + OFF_MN);   // 128

    const int tid  = threadIdx.x;
    const int warp = tid >> 5;
    const int lane = tid & 31;
    const int wm = warp >> 2;        // 0..1
    const int wn = warp & 3;         // 0..3
    const int tq = lane >> 2;        // 0..7
    const int tr = lane & 3;         // 0..3
    const int gp0 = blockIdx.x * BM;
    const float alpha  = 15.0f / md[0];
    const float alpha2 = 2.0f * alpha;

    // ---- cp.async chunk loader: 256 codes x 64 halves -> ring slot S&1 ----
    auto issue = [&](int S) {
        int t = S >> 3, sub = S & 7, chunk = sub >> 1, split = sub & 1;
        const __half* src = (split ? g_eloP : g_ehiP)
                          + (size_t)t*BN*CC + chunk*64;
        __half* dstB = Bbuf + (size_t)(S & 1)*CHUNK_HALVES;
        #pragma unroll
        for (int it = 0; it < 8; ++it) {
            int lin = it*256 + tid;
            int row = lin >> 3, seg = lin & 7;
            const __half* sp2 = src + (size_t)row*CC + seg*8;
            unsigned d = (unsigned)__cvta_generic_to_shared(dstB + row*BSTR + seg*8);
            asm volatile("cp.async.cg.shared.global [%0], [%1], 16;"
                         :: "r"(d), "l"(sp2) : "memory");
        }
        asm volatile("cp.async.commit_group;" ::: "memory");
    };

    issue(0);   // overlap first chunk with feature load

    // ---- load + split features (128 pixels x 256 ch), accumulate f2 ----
    {
        int p = tid & 127;
        int q = tid >> 7;                    // 0/1 -> channel half
        int gp = gp0 + p;
        int b  = gp / PPB;
        int r  = gp - b*PPB;
        int h  = r / OH, w = r - h*OH;
        const float* fb = feat + ((size_t)b*CC*HIN + (h+1))*HIN + (w+1);
        float p2 = 0.f;
        #pragma unroll 4
        for (int cp = q*64; cp < q*64 + 64; ++cp) {
            float v0 = fb[(size_t)(2*cp)   * (HIN*HIN)];
            float v1 = fb[(size_t)(2*cp+1) * (HIN*HIN)];
            p2 += v0*v0 + v1*v1;
            __half h0 = __float2half_rn(v0), h1 = __float2half_rn(v1);
            __half l0 = __float2half_rn(v0 - __half2float(h0));
            __half l1 = __float2half_rn(v1 - __half2float(h1));
            int jp = cp & 7, grp = cp >> 3;
            int phys = grp*16 + (((jp & 3) << 1) + (jp >> 2)) * 2;
            *(__half2*)&Ah[p*ASTR + phys] = __halves2half2(h0, h1);
            *(__half2*)&Al[p*ASTR + phys] = __halves2half2(l0, l1);
        }
        mpart[tid] = p2;
    }
    __syncthreads();
    if (tid < 128) {
        f2s[tid]   = -alpha * (mpart[tid] + mpart[128 + tid]);
        m_run[tid] = -1e30f;
        s_run[tid] = 0.f;
    }

    float acc[4][8][4];

    for (int S = 0; S < NSTAGE; ++S) {
        const int t = S >> 3, c = S & 7;
        const int split = c & 1;

        asm volatile("cp.async.wait_group 0;" ::: "memory");
        __syncthreads();
        if (S + 1 < NSTAGE) issue(S + 1);

        if (c == 0) {
            #pragma unroll
            for (int mt = 0; mt < 4; ++mt)
                #pragma unroll
                for (int nt = 0; nt < 8; ++nt)
                    #pragma unroll
                    for (int i = 0; i < 4; ++i) acc[mt][nt][i] = 0.f;
            e2s[tid] = -alpha * g_e2[t*BN + tid];
        }

        // ---- mma on chunk in slot S&1; B fragments shared across passes ----
        const __half* B = Bbuf + (size_t)(S & 1)*CHUNK_HALVES;
        const int kc = (c >> 1) * 64;
        #pragma unroll
        for (int g = 0; g < 4; ++g) {
            uint2 z[8];
            #pragma unroll
            for (int nt = 0; nt < 8; ++nt)
                z[nt] = *(const uint2*)&B[(wn*64 + nt*8 + tq)*BSTR + g*16 + 4*tr];
            unsigned afrH[4][4];
            #pragma unroll
            for (int mt = 0; mt < 4; ++mt) {
                int row = wm*64 + mt*16 + tq;
                uint2 x = *(const uint2*)&Ah[row*ASTR + kc + g*16 + 4*tr];
                uint2 y = *(const uint2*)&Ah[(row+8)*ASTR + kc + g*16 + 4*tr];
                afrH[mt][0] = x.x; afrH[mt][1] = y.x;
                afrH[mt][2] = x.y; afrH[mt][3] = y.y;
            }
            if (split == 0) {
                unsigned afrL[4][4];
                #pragma unroll
                for (int mt = 0; mt < 4; ++mt) {
                    int row = wm*64 + mt*16 + tq;
                    uint2 x = *(const uint2*)&Al[row*ASTR + kc + g*16 + 4*tr];
                    uint2 y = *(const uint2*)&Al[(row+8)*ASTR + kc + g*16 + 4*tr];
                    afrL[mt][0] = x.x; afrL[mt][1] = y.x;
                    afrL[mt][2] = x.y; afrL[mt][3] = y.y;
                }
                #pragma unroll
                for (int nt = 0; nt < 8; ++nt)
                    #pragma unroll
                    for (int mt = 0; mt < 4; ++mt) {
                        mma16816(acc[mt][nt], afrH[mt], z[nt].x, z[nt].y);
                        mma16816(acc[mt][nt], afrL[mt], z[nt].x, z[nt].y);
                    }
            } else {
                #pragma unroll
                for (int nt = 0; nt < 8; ++nt)
                    #pragma unroll
                    for (int mt = 0; mt < 4; ++mt)
                        mma16816(acc[mt][nt], afrH[mt], z[nt].x, z[nt].y);
            }
        }

        // ---- epilogue at last chunk of tile: logits, softmax, store ----
        if (c == 7) {
            float rmax[8];
            #pragma unroll
            for (int i = 0; i < 8; ++i) rmax[i] = -1e30f;
            #pragma unroll
            for (int mt = 0; mt < 4; ++mt) {
                int r0 = wm*64 + mt*16 + tq;
                float fa = f2s[r0], fb2 = f2s[r0 + 8];
                #pragma unroll
                for (int nt = 0; nt < 8; ++nt) {
                    int nl = wn*64 + nt*8 + 2*tr;
                    float e0 = e2s[nl], e1 = e2s[nl + 1];
                    float l0 = fmaf(alpha2, acc[mt][nt][0], fa  + e0);
                    float l1 = fmaf(alpha2, acc[mt][nt][1], fa  + e1);
                    float l2 = fmaf(alpha2, acc[mt][nt][2], fb2 + e0);
                    float l3 = fmaf(alpha2, acc[mt][nt][3], fb2 + e1);
                    acc[mt][nt][0] = l0; acc[mt][nt][1] = l1;
                    acc[mt][nt][2] = l2; acc[mt][nt][3] = l3;
                    rmax[2*mt]   = fmaxf(rmax[2*mt],   fmaxf(l0, l1));
                    rmax[2*mt+1] = fmaxf(rmax[2*mt+1], fmaxf(l2, l3));
                }
            }
            #pragma unroll
            for (int i = 0; i < 8; ++i) {
                rmax[i] = fmaxf(rmax[i], __shfl_xor_sync(0xffffffffu, rmax[i], 1));
                rmax[i] = fmaxf(rmax[i], __shfl_xor_sync(0xffffffffu, rmax[i], 2));
            }
            if (tr == 0) {
                #pragma unroll
                for (int i = 0; i < 8; ++i) {
                    int row = wm*64 + (i >> 1)*16 + tq + (i & 1)*8;
                    mpart[wn*128 + row] = rmax[i];
                }
            }
            __syncthreads();
            if (tid < 128) {
                float mm = fmaxf(fmaxf(mpart[tid], mpart[128 + tid]),
                                 fmaxf(mpart[256 + tid], mpart[384 + tid]));
                mnew[tid] = fmaxf(mm, m_run[tid]);
            }
            __syncthreads();

            float rsum[8];
            #pragma unroll
            for (int i = 0; i < 8; ++i) rsum[i] = 0.f;
            #pragma unroll
            for (int mt = 0; mt < 4; ++mt) {
                int r0 = wm*64 + mt*16 + tq;
                int r1 = r0 + 8;
                int gpa = gp0 + r0, gpb = gp0 + r1;
                int ba = gpa / PPB, bb = gpb / PPB;
                size_t base0 = (size_t)BOWOFF + (size_t)ba*NK*PPB + (gpa - ba*PPB);
                size_t base1 = (size_t)BOWOFF + (size_t)bb*NK*PPB + (gpb - bb*PPB);
                float mn0 = mnew[r0], mn1 = mnew[r1];
                #pragma unroll
                for (int nt = 0; nt < 8; ++nt) {
                    int ng = t*BN + wn*64 + nt*8 + 2*tr;
                    float l0 = acc[mt][nt][0], l1 = acc[mt][nt][1];
                    float l2 = acc[mt][nt][2], l3 = acc[mt][nt][3];
                    rsum[2*mt]   += __expf(l0 - mn0) + __expf(l1 - mn0);
                    rsum[2*mt+1] += __expf(l2 - mn1) + __expf(l3 - mn1);
                    out[base0 + (size_t)ng*PPB]       = l0;
                    out[base0 + (size_t)(ng+1)*PPB]   = l1;
                    out[base1 + (size_t)ng*PPB]       = l2;
                    out[base1 + (size_t)(ng+1)*PPB]   = l3;
                }
            }
            #pragma unroll
            for (int i = 0; i < 8; ++i) {
                rsum[i] += __shfl_xor_sync(0xffffffffu, rsum[i], 1);
                rsum[i] += __shfl_xor_sync(0xffffffffu, rsum[i], 2);
            }
            if (tr == 0) {
                #pragma unroll
                for (int i = 0; i < 8; ++i) {
                    int row = wm*64 + (i >> 1)*16 + tq + (i & 1)*8;
                    spart[wn*128 + row] = rsum[i];
                }
            }
            __syncthreads();
            if (tid < 128) {
                float ss = spart[tid] + spart[128 + tid]
                         + spart[256 + tid] + spart[384 + tid];
                s_run[tid] = s_run[tid]*__expf(m_run[tid] - mnew[tid]) + ss;
                m_run[tid] = mnew[tid];
            }
        }
    }

    // ---- fused fix-up: exp(l-m)/s in place (reads own writes via L2),
    //      deterministic per-block bow partials (two batch segments) ----
    __syncthreads();
    if (tid < 128) mnew[tid] = __frcp_rn(s_run[tid]);
    __syncthreads();

    const int b0  = gp0 / PPB;
    const int cut = min(PPB - (gp0 - b0*PPB), BM);
    for (int n = warp; n < NK; n += 8) {
        float a0 = 0.f, a1 = 0.f;
        #pragma unroll
        for (int h2 = 0; h2 < 4; ++h2) {
            int p  = lane + 32*h2;
            int gp = gp0 + p;
            int bb = b0 + (p >= cut);
            int pr = gp - bb*PPB;
            size_t addr = (size_t)BOWOFF + ((size_t)bb*NK + n)*PPB + pr;
            float v = __expf(out[addr] - m_run[p]) * mnew[p];
            out[addr] = v;
            if (p < cut) a0 += v; else a1 += v;
        }
        #pragma unroll
        for (int o = 16; o; o >>= 1) {
            a0 += __shfl_xor_sync(0xffffffffu, a0, o);
            a1 += __shfl_xor_sync(0xffffffffu, a1, o);
        }
        if (lane == 0) {
            g_bowp[0][blockIdx.x][n] = a0;
            g_bowp[1][blockIdx.x][n] = a1;
        }
    }
}

// ---------------------------------------------------------------------------
// Pass 3: bow = mean over pixels, L1-normalized. Sums per-block partials.
// ---------------------------------------------------------------------------
__global__ __launch_bounds__(256)
void pass3_kernel(float* __restrict__ out) {
    __shared__ float redw[8];
    __shared__ float denom_s;
    const int b   = blockIdx.x;
    const int tid = threadIdx.x;
    const float invP = 1.0f / (float)PPB;

    const int j0 = (PPB*b) / BM;
    const int j1 = (PPB*b + PPB - 1) / BM;

    float vals[NK/256];
    float tot = 0.f;
    #pragma unroll
    for (int i = 0; i < NK/256; ++i) {
        int k = tid + 256*i;
        float s = 0.f;
        for (int j = j0; j <= j1; ++j) {
            int bj = (j*BM) / PPB;
            s += (bj == b) ? g_bowp[0][j][k] : g_bowp[1][j][k];
        }
        vals[i] = s * invP;
        tot += vals[i];
    }
    #pragma unroll
    for (int o = 16; o; o >>= 1) tot += __shfl_xor_sync(0xffffffffu, tot, o);
    if ((tid & 31) == 0) redw[tid >> 5] = tot;
    __syncthreads();
    if (tid == 0) {
        float t = 0.f;
        #pragma unroll
        for (int i = 0; i < 8; i++) t += redw[i];
        denom_s = fmaxf(t, 1e-12f);
    }
    __syncthreads();
    const float den = denom_s;
    #pragma unroll
    for (int i = 0; i < NK/256; ++i)
        out[b*NK + tid + 256*i] = vals[i] / den;
}

// ---------------------------------------------------------------------------
extern "C" void kernel_launch(void* const* d_in, const int* in_sizes, int n_in,
                              void* d_out, int out_size) {
    const float* feat = (const float*)d_in[0];   // (32,256,30,30)
    const float* emb  = (const float*)d_in[1];   // (2048,256)
    const float* md   = (const float*)d_in[2];   // (1,)
    float* out = (float*)d_out;                  // [bow 65536 | codes]

    cudaFuncSetAttribute(pass1_kernel,
                         cudaFuncAttributeMaxDynamicSharedMemorySize, SMEM_BYTES);

    e2_kernel   <<<NK/8, 256>>>(emb);
    split_kernel<<<NK*CC/2/256, 256>>>(emb);
    pass1_kernel<<<NBLK, 256, SMEM_BYTES>>>(feat, md, out);
    pass3_kernel<<<BB, 256>>>(out);
    (void)in_sizes; (void)n_in; (void)out_size;
}

// round 5
// speedup vs baseline: 2.5989x; 2.5989x over previous
#include <cuda_runtime.h>
#include <cuda_fp16.h>
#include <math.h>

// Problem constants
#define BB   32
#define CC   256
#define HIN  30
#define OH   28
#define PPB  784
#define NPIX 25088
#define NK   2048
#define BOWOFF (BB*NK)

// Pass-1 tiling (tensor-core)
#define BM 64           // pixels per block
#define BN 256          // codes per tile
#define KC 64           // k-chunk (halves)
#define NTILE (NK/BN)   // 8
#define NSTAGE (NTILE*4*2) // 64 load stages (4 chunks x {hi,lo})
#define ASTR 272        // A smem row stride (halves): conflict-free
#define BSTR 80         // B smem row stride (halves): conflict-free
#define LSTR2 66        // lbuf row stride (floats)

// smem byte offsets
#define OFF_AL   34816
#define OFF_B0   69632
#define OFF_B1   110592
#define OFF_LBUF 151552
#define OFF_MISC 219136
#define SMEM1_BYTES 221696

// Scratch
__device__ float g_e2[NK];
__device__ float g_pixmax[NPIX];
__device__ float g_pixsum[NPIX];
__device__ float g_bow[BB*NK];
__device__ __align__(16) __half g_ehiP[NK*CC];  // k-permuted fp16 hi split
__device__ __align__(16) __half g_eloP[NK*CC];  // k-permuted fp16 lo split

// ---------------------------------------------------------------------------
__device__ __forceinline__ void mma16816(float* c, const unsigned* a,
                                         unsigned b0, unsigned b1) {
    asm volatile(
        "mma.sync.aligned.m16n8k16.row.col.f32.f16.f16.f32 "
        "{%0,%1,%2,%3}, {%4,%5,%6,%7}, {%8,%9}, {%0,%1,%2,%3};"
        : "+f"(c[0]), "+f"(c[1]), "+f"(c[2]), "+f"(c[3])
        : "r"(a[0]), "r"(a[1]), "r"(a[2]), "r"(a[3]), "r"(b0), "r"(b1));
}

// ---------------------------------------------------------------------------
// Pass 0a: e2[k] = sum_c e[k][c]^2
// ---------------------------------------------------------------------------
__global__ void e2_kernel(const float* __restrict__ emb) {
    int gw = blockIdx.x * (blockDim.x >> 5) + (threadIdx.x >> 5);
    int lane = threadIdx.x & 31;
    if (gw >= NK) return;
    const float4* row = reinterpret_cast<const float4*>(emb + (size_t)gw * CC);
    float s = 0.f;
    #pragma unroll
    for (int i = lane; i < CC/4; i += 32) {
        float4 v = row[i];
        s += v.x*v.x + v.y*v.y + v.z*v.z + v.w*v.w;
    }
    #pragma unroll
    for (int o = 16; o; o >>= 1) s += __shfl_xor_sync(0xffffffffu, s, o);
    if (lane == 0) g_e2[gw] = s;
}

// ---------------------------------------------------------------------------
// Pass 0b: fp16 hi/lo split of embedding, k-permuted fragment layout
// ---------------------------------------------------------------------------
__global__ void split_kernel(const float* __restrict__ emb) {
    int idx = blockIdx.x * 256 + threadIdx.x;     // over NK*CC/2 pairs
    if (idx >= NK*(CC/2)) return;
    int k  = idx >> 7;
    int cp = idx & 127;
    float v0 = emb[k*CC + 2*cp];
    float v1 = emb[k*CC + 2*cp + 1];
    __half h0 = __float2half_rn(v0), h1 = __float2half_rn(v1);
    __half l0 = __float2half_rn(v0 - __half2float(h0));
    __half l1 = __float2half_rn(v1 - __half2float(h1));
    int jp = cp & 7, grp = cp >> 3;
    int phys = grp*16 + (((jp & 3) << 1) + (jp >> 2)) * 2;
    *(__half2*)&g_ehiP[(size_t)k*CC + phys] = __halves2half2(h0, h1);
    *(__half2*)&g_eloP[(size_t)k*CC + phys] = __halves2half2(l0, l1);
}

// ---------------------------------------------------------------------------
// Pass 1: block = 64 pixels x all 2048 codes via fp16-split HMMA.
// 8 warps as 2m x 4n; warp tile 32m x 64n; acc fp32 [2][8][4].
// B fragments shared across Ah/Al passes (z loaded once per g).
// ---------------------------------------------------------------------------
extern __shared__ float smem1[];

__global__ __launch_bounds__(256, 1)
void pass1_kernel(const float* __restrict__ feat,
                  const float* __restrict__ md,
                  float* __restrict__ out)
{
    char* smem_raw = (char*)smem1;
    __half* Ah    = (__half*)smem_raw;               // [64][272]
    __half* Al    = (__half*)(smem_raw + OFF_AL);    // [64][272]
    __half* Bb0   = (__half*)(smem_raw + OFF_B0);    // [256][80]
    __half* Bb1   = (__half*)(smem_raw + OFF_B1);    // [256][80]
    float*  lbuf  = (float*)(smem_raw + OFF_LBUF);   // [256][66]
    float*  f2s   = (float*)(smem_raw + OFF_MISC);   // 64  (-alpha*f2)
    float*  e2s   = f2s + 64;                        // 256 (-alpha*e2)
    float*  mnew  = e2s + 256;                       // 64
    float*  red   = mnew + 64;                       // 256

    const int tid  = threadIdx.x;
    const int warp = tid >> 5;
    const int lane = tid & 31;
    const int wm = warp >> 2;        // 0..1
    const int wn = warp & 3;         // 0..3
    const int tq = lane >> 2;        // 0..7
    const int tr = lane & 3;         // 0..3
    const int gp0 = blockIdx.x * BM;
    const float alpha  = 15.0f / md[0];
    const float alpha2 = 2.0f * alpha;

    // ---- issue helper: one B split-chunk (40 KB) via cp.async ----
    auto issue = [&](int s) {
        int tile = s >> 3, sub = s & 7;
        int chunk = sub >> 1, split = sub & 1;
        const __half* src = (split ? g_eloP : g_ehiP)
                          + (size_t)tile*BN*CC + chunk*KC;
        __half* dstB = (s & 1) ? Bb1 : Bb0;
        #pragma unroll
        for (int it = 0; it < 8; ++it) {
            int lin = it*256 + tid;
            int row = lin >> 3, seg = lin & 7;
            const __half* sp = src + row*CC + seg*8;
            unsigned d = (unsigned)__cvta_generic_to_shared(dstB + row*BSTR + seg*8);
            asm volatile("cp.async.cg.shared.global [%0], [%1], 16;"
                         :: "r"(d), "l"(sp) : "memory");
        }
        asm volatile("cp.async.commit_group;" ::: "memory");
    };

    issue(0);   // prefetch first B chunk ASAP

    // ---- load + split features, accumulate f2 ----
    {
        int p  = tid & 63;
        int q4 = tid >> 6;
        int gp = gp0 + p;
        int b  = gp / PPB;
        int r  = gp - b*PPB;
        int h  = r / OH, w = r - h*OH;
        const float* fb = feat + (size_t)b*CC*HIN*HIN + (h+1)*HIN + (w+1);
        float p2 = 0.f;
        for (int cp = q4; cp < 128; cp += 4) {
            float v0 = fb[(2*cp)*HIN*HIN];
            float v1 = fb[(2*cp+1)*HIN*HIN];
            p2 += v0*v0 + v1*v1;
            __half h0 = __float2half_rn(v0), h1 = __float2half_rn(v1);
            __half l0 = __float2half_rn(v0 - __half2float(h0));
            __half l1 = __float2half_rn(v1 - __half2float(h1));
            int jp = cp & 7, grp = cp >> 3;
            int phys = grp*16 + (((jp & 3) << 1) + (jp >> 2)) * 2;
            *(__half2*)&Ah[p*ASTR + phys] = __halves2half2(h0, h1);
            *(__half2*)&Al[p*ASTR + phys] = __halves2half2(l0, l1);
        }
        red[q4*64 + p] = p2;
    }
    __syncthreads();
    if (tid < 64)
        f2s[tid] = -alpha * (red[tid] + red[64+tid] + red[128+tid] + red[192+tid]);

    float m_run = -1e30f, s_run = 0.f;
    float acc[2][8][4];

    for (int s = 0; s < NSTAGE; ++s) {
        const int tile  = s >> 3;
        const int sub   = s & 7;
        const int chunk = sub >> 1;
        const int split = sub & 1;
        const __half* B = (s & 1) ? Bb1 : Bb0;

        asm volatile("cp.async.wait_group 0;" ::: "memory");
        __syncthreads();

        if (sub == 0) {
            #pragma unroll
            for (int mt = 0; mt < 2; ++mt)
                #pragma unroll
                for (int nt = 0; nt < 8; ++nt)
                    #pragma unroll
                    for (int i = 0; i < 4; ++i) acc[mt][nt][i] = 0.f;
            e2s[tid] = -alpha * g_e2[tile*BN + tid];
        }
        if (s + 1 < NSTAGE) issue(s + 1);

        // ---- mma: hi stage -> (Ah+Al)·Bhi sharing z; lo stage -> Ah·Blo ----
        const int kc = chunk * KC;
        #pragma unroll
        for (int g = 0; g < 4; ++g) {
            uint2 z[8];
            #pragma unroll
            for (int nt = 0; nt < 8; ++nt)
                z[nt] = *(const uint2*)&B[(wn*64 + nt*8 + tq)*BSTR + g*16 + 4*tr];

            unsigned afrH[2][4];
            #pragma unroll
            for (int mt = 0; mt < 2; ++mt) {
                int row = wm*32 + mt*16 + tq;
                uint2 x = *(const uint2*)&Ah[row*ASTR + kc + g*16 + 4*tr];
                uint2 y = *(const uint2*)&Ah[(row+8)*ASTR + kc + g*16 + 4*tr];
                afrH[mt][0] = x.x; afrH[mt][1] = y.x;
                afrH[mt][2] = x.y; afrH[mt][3] = y.y;
            }
            #pragma unroll
            for (int nt = 0; nt < 8; ++nt) {
                mma16816(acc[0][nt], afrH[0], z[nt].x, z[nt].y);
                mma16816(acc[1][nt], afrH[1], z[nt].x, z[nt].y);
            }
            if (split == 0) {
                unsigned afrL[2][4];
                #pragma unroll
                for (int mt = 0; mt < 2; ++mt) {
                    int row = wm*32 + mt*16 + tq;
                    uint2 x = *(const uint2*)&Al[row*ASTR + kc + g*16 + 4*tr];
                    uint2 y = *(const uint2*)&Al[(row+8)*ASTR + kc + g*16 + 4*tr];
                    afrL[mt][0] = x.x; afrL[mt][1] = y.x;
                    afrL[mt][2] = x.y; afrL[mt][3] = y.y;
                }
                #pragma unroll
                for (int nt = 0; nt < 8; ++nt) {
                    mma16816(acc[0][nt], afrL[0], z[nt].x, z[nt].y);
                    mma16816(acc[1][nt], afrL[1], z[nt].x, z[nt].y);
                }
            }
        }

        if (sub == 7) {
            // ---- stage logits to lbuf[n][m] ----
            #pragma unroll
            for (int mt = 0; mt < 2; ++mt) {
                int m0 = wm*32 + mt*16 + tq;
                float c1a = f2s[m0], c1b = f2s[m0+8];
                #pragma unroll
                for (int nt = 0; nt < 8; ++nt) {
                    int n0 = wn*64 + nt*8 + 2*tr;
                    float e0 = e2s[n0], e1 = e2s[n0+1];
                    lbuf[n0*LSTR2 + m0]       = fmaf(alpha2, acc[mt][nt][0], c1a + e0);
                    lbuf[(n0+1)*LSTR2 + m0]   = fmaf(alpha2, acc[mt][nt][1], c1a + e1);
                    lbuf[n0*LSTR2 + m0+8]     = fmaf(alpha2, acc[mt][nt][2], c1b + e0);
                    lbuf[(n0+1)*LSTR2 + m0+8] = fmaf(alpha2, acc[mt][nt][3], c1b + e1);
                }
            }
            __syncthreads();

            // ---- per-pixel online softmax over this tile's 256 codes ----
            const int p = tid & 63, q = tid >> 6;
            float mloc = -1e30f;
            #pragma unroll 8
            for (int i = 0; i < 64; ++i)
                mloc = fmaxf(mloc, lbuf[(q + 4*i)*LSTR2 + p]);
            red[q*64 + p] = mloc;
            __syncthreads();
            if (q == 0) {
                float mm = fmaxf(fmaxf(red[p], red[64+p]),
                                 fmaxf(red[128+p], red[192+p]));
                mnew[p] = fmaxf(mm, m_run);
            }
            __syncthreads();
            float mn = mnew[p];
            float sloc = 0.f;
            #pragma unroll 8
            for (int i = 0; i < 64; ++i)
                sloc += __expf(lbuf[(q + 4*i)*LSTR2 + p] - mn);
            red[q*64 + p] = sloc;
            __syncthreads();
            if (q == 0) {
                float ss = red[p] + red[64+p] + red[128+p] + red[192+p];
                s_run = s_run * __expf(m_run - mn) + ss;
                m_run = mn;
            }

            // ---- coalesced logit store: codes[b][k][h][w] ----
            for (int t2 = tid; t2 < BN*BM; t2 += 256) {
                int n = t2 >> 6, mm = t2 & 63;
                int gp = gp0 + mm;
                int b  = gp / PPB, r = gp - b*PPB;
                out[BOWOFF + ((size_t)(b*NK + tile*BN + n))*PPB + r] =
                    lbuf[n*LSTR2 + mm];
            }
            __syncthreads();   // protect lbuf before next tile's staging
        }
    }

    if (tid < 64) {
        g_pixmax[gp0 + tid] = m_run;
        g_pixsum[gp0 + tid] = s_run;
    }
}

// ---------------------------------------------------------------------------
// Pass 2: codes = exp(l - m) / s (in place). One warp per code, 8 codes per
// block, no block syncs in the stream loop.
// ---------------------------------------------------------------------------
__global__ __launch_bounds__(256)
void pass2_kernel(float* __restrict__ out) {
    __shared__ __align__(16) float sm[PPB];
    __shared__ __align__(16) float ss[PPB];

    const int b  = blockIdx.x >> 8;          // 256 blocks per batch
    const int k0 = (blockIdx.x & 255) * 8;
    const int tid = threadIdx.x;

    const float* gm = g_pixmax + b*PPB;
    const float* gs = g_pixsum + b*PPB;
    for (int t = tid; t < PPB; t += 256) {
        sm[t] = gm[t];
        ss[t] = __frcp_rn(gs[t]);
    }
    __syncthreads();

    const int w = tid >> 5, lane = tid & 31;
    const int k = k0 + w;
    float4* p = reinterpret_cast<float4*>(out + (size_t)BOWOFF + ((size_t)(b*NK + k))*PPB);
    const float4* m4p = reinterpret_cast<const float4*>(sm);
    const float4* s4p = reinterpret_cast<const float4*>(ss);

    float acc = 0.f;
    #pragma unroll 2
    for (int t = lane; t < PPB/4; t += 32) {
        float4 v  = p[t];
        float4 m4 = m4p[t];
        float4 s4 = s4p[t];
        v.x = __expf(v.x - m4.x) * s4.x;
        v.y = __expf(v.y - m4.y) * s4.y;
        v.z = __expf(v.z - m4.z) * s4.z;
        v.w = __expf(v.w - m4.w) * s4.w;
        p[t] = v;
        acc += (v.x + v.y) + (v.z + v.w);
    }
    #pragma unroll
    for (int o = 16; o; o >>= 1) acc += __shfl_xor_sync(0xffffffffu, acc, o);
    if (lane == 0) g_bow[b*NK + k] = acc;
}

// ---------------------------------------------------------------------------
// Pass 3: bow normalize
// ---------------------------------------------------------------------------
__global__ __launch_bounds__(256)
void pass3_kernel(float* __restrict__ out) {
    __shared__ float redw[8];
    __shared__ float denom_s;
    int b   = blockIdx.x;
    int tid = threadIdx.x;
    const float invP = 1.0f / (float)PPB;

    float acc = 0.f;
    for (int k = tid; k < NK; k += 256) acc += g_bow[b*NK + k] * invP;
    #pragma unroll
    for (int o = 16; o; o >>= 1) acc += __shfl_xor_sync(0xffffffffu, acc, o);
    if ((tid & 31) == 0) redw[tid >> 5] = acc;
    __syncthreads();
    if (tid == 0) {
        float t = 0.f;
        #pragma unroll
        for (int i = 0; i < 8; i++) t += redw[i];
        denom_s = fmaxf(t, 1e-12f);
    }
    __syncthreads();
    float den = denom_s;
    for (int k = tid; k < NK; k += 256)
        out[b*NK + k] = (g_bow[b*NK + k] * invP) / den;
}

// ---------------------------------------------------------------------------
extern "C" void kernel_launch(void* const* d_in, const int* in_sizes, int n_in,
                              void* d_out, int out_size) {
    const float* feat = (const float*)d_in[0];   // (32,256,30,30)
    const float* emb  = (const float*)d_in[1];   // (2048,256)
    const float* md   = (const float*)d_in[2];   // (1,)
    float* out = (float*)d_out;

    cudaFuncSetAttribute(pass1_kernel,
                         cudaFuncAttributeMaxDynamicSharedMemorySize, SMEM1_BYTES);

    e2_kernel   <<<NK/8, 256>>>(emb);
    split_kernel<<<NK*CC/2/256, 256>>>(emb);
    pass1_kernel<<<NPIX/BM, 256, SMEM1_BYTES>>>(feat, md, out);
    pass2_kernel<<<BB*NK/8, 256>>>(out);
    pass3_kernel<<<BB, 256>>>(out);
    (void)in_sizes; (void)n_in; (void)out_size;
}

// round 6
// speedup vs baseline: 2.7603x; 1.0621x over previous
#include <cuda_runtime.h>
#include <cuda_fp16.h>
#include <math.h>

// Problem constants
#define BB   32
#define CC   256
#define HIN  30
#define OH   28
#define PPB  784
#define NPIX 25088
#define NK   2048
#define BOWOFF (BB*NK)

// Pass-1 tiling (tensor-core)
#define BM 64            // pixels per block
#define BN 256           // codes per tile
#define KC 32            // k-chunk (halves)
#define NTILE (NK/BN)    // 8
#define NSTAGE (NTILE*16)// 128 stages: 8 chunks x {hi,lo} per tile
#define ASTR 272         // A smem row stride (halves)
#define BSTR 40          // B smem row stride (halves), conflict-free (half-warp)
#define CHUNK_BYTES (BN*BSTR*2)   // 20480

// smem byte offsets (total 112 KB -> 2 blocks/SM)
#define OFF_AL   34816
#define OFF_B0   69632
#define OFF_B1   90112
#define OFF_F2   110592
#define OFF_E2   110848
#define OFF_MN   111872
#define OFF_MR   112128
#define OFF_SR   112384
#define OFF_MP   112640
#define OFF_SP   113664
#define SMEM1_BYTES 114688

// Scratch
__device__ float g_e2[NK];
__device__ float g_pixmax[NPIX];
__device__ float g_pixsum[NPIX];
__device__ float g_bow[BB*NK];
__device__ __align__(16) __half g_ehiP[NK*CC];  // k-permuted fp16 hi split
__device__ __align__(16) __half g_eloP[NK*CC];  // k-permuted fp16 lo split

// ---------------------------------------------------------------------------
__device__ __forceinline__ void mma16816(float* c, const unsigned* a,
                                         unsigned b0, unsigned b1) {
    asm volatile(
        "mma.sync.aligned.m16n8k16.row.col.f32.f16.f16.f32 "
        "{%0,%1,%2,%3}, {%4,%5,%6,%7}, {%8,%9}, {%0,%1,%2,%3};"
        : "+f"(c[0]), "+f"(c[1]), "+f"(c[2]), "+f"(c[3])
        : "r"(a[0]), "r"(a[1]), "r"(a[2]), "r"(a[3]), "r"(b0), "r"(b1));
}

// ---------------------------------------------------------------------------
// Pass 0a: e2[k] = sum_c e[k][c]^2
// ---------------------------------------------------------------------------
__global__ void e2_kernel(const float* __restrict__ emb) {
    int gw = blockIdx.x * (blockDim.x >> 5) + (threadIdx.x >> 5);
    int lane = threadIdx.x & 31;
    if (gw >= NK) return;
    const float4* row = reinterpret_cast<const float4*>(emb + (size_t)gw * CC);
    float s = 0.f;
    #pragma unroll
    for (int i = lane; i < CC/4; i += 32) {
        float4 v = row[i];
        s += v.x*v.x + v.y*v.y + v.z*v.z + v.w*v.w;
    }
    #pragma unroll
    for (int o = 16; o; o >>= 1) s += __shfl_xor_sync(0xffffffffu, s, o);
    if (lane == 0) g_e2[gw] = s;
}

// ---------------------------------------------------------------------------
// Pass 0b: fp16 hi/lo split of embedding, k-permuted fragment layout
// ---------------------------------------------------------------------------
__global__ void split_kernel(const float* __restrict__ emb) {
    int idx = blockIdx.x * 256 + threadIdx.x;     // over NK*CC/2 pairs
    if (idx >= NK*(CC/2)) return;
    int k  = idx >> 7;
    int cp = idx & 127;
    float v0 = emb[k*CC + 2*cp];
    float v1 = emb[k*CC + 2*cp + 1];
    __half h0 = __float2half_rn(v0), h1 = __float2half_rn(v1);
    __half l0 = __float2half_rn(v0 - __half2float(h0));
    __half l1 = __float2half_rn(v1 - __half2float(h1));
    int jp = cp & 7, grp = cp >> 3;
    int phys = grp*16 + (((jp & 3) << 1) + (jp >> 2)) * 2;
    *(__half2*)&g_ehiP[(size_t)k*CC + phys] = __halves2half2(h0, h1);
    *(__half2*)&g_eloP[(size_t)k*CC + phys] = __halves2half2(l0, l1);
}

// ---------------------------------------------------------------------------
// Pass 1: block = 64 pixels x all 2048 codes via fp16-split HMMA, occ=2.
// 8 warps as 2m x 4n; warp tile 32m x 64n; acc fp32 [2][8][4].
// Register epilogue: per-row max/sum via shuffles, direct STG logit stores.
// ---------------------------------------------------------------------------
extern __shared__ float smem1[];

__global__ __launch_bounds__(256, 2)
void pass1_kernel(const float* __restrict__ feat,
                  const float* __restrict__ md,
                  float* __restrict__ out)
{
    char* smem_raw = (char*)smem1;
    __half* Ah    = (__half*)smem_raw;               // [64][272]
    __half* Al    = (__half*)(smem_raw + OFF_AL);    // [64][272]
    __half* Bb0   = (__half*)(smem_raw + OFF_B0);    // [256][40]
    __half* Bb1   = (__half*)(smem_raw + OFF_B1);    // [256][40]
    float*  f2s   = (float*)(smem_raw + OFF_F2);     // 64  (-alpha*f2)
    float*  e2s   = (float*)(smem_raw + OFF_E2);     // 256 (-alpha*e2)
    float*  mnew  = (float*)(smem_raw + OFF_MN);     // 64
    float*  m_run = (float*)(smem_raw + OFF_MR);     // 64
    float*  s_run = (float*)(smem_raw + OFF_SR);     // 64
    float*  mpart = (float*)(smem_raw + OFF_MP);     // 4 x 64
    float*  spart = (float*)(smem_raw + OFF_SP);     // 4 x 64
    float*  red   = mpart;                           // alias (prologue only)

    const int tid  = threadIdx.x;
    const int warp = tid >> 5;
    const int lane = tid & 31;
    const int wm = warp >> 2;        // 0..1
    const int wn = warp & 3;         // 0..3
    const int tq = lane >> 2;        // 0..7
    const int tr = lane & 3;         // 0..3
    const int gp0 = blockIdx.x * BM;
    const float alpha  = 15.0f / md[0];
    const float alpha2 = 2.0f * alpha;

    // ---- issue helper: one B split-chunk (20 KB) via cp.async ----
    auto issue = [&](int s) {
        int tile = s >> 4, sub = s & 15;
        int chunk = sub >> 1, split = sub & 1;
        const __half* src = (split ? g_eloP : g_ehiP)
                          + (size_t)tile*BN*CC + chunk*KC;
        __half* dstB = (s & 1) ? Bb1 : Bb0;
        #pragma unroll
        for (int it = 0; it < 4; ++it) {
            int lin = it*256 + tid;
            int row = lin >> 2, seg = lin & 3;
            const __half* sp = src + row*CC + seg*8;
            unsigned d = (unsigned)__cvta_generic_to_shared(dstB + row*BSTR + seg*8);
            asm volatile("cp.async.cg.shared.global [%0], [%1], 16;"
                         :: "r"(d), "l"(sp) : "memory");
        }
        asm volatile("cp.async.commit_group;" ::: "memory");
    };

    issue(0);   // prefetch first B chunk ASAP

    // ---- load + split features, accumulate f2 ----
    {
        int p  = tid & 63;
        int q4 = tid >> 6;
        int gp = gp0 + p;
        int b  = gp / PPB;
        int r  = gp - b*PPB;
        int h  = r / OH, w = r - h*OH;
        const float* fb = feat + (size_t)b*CC*HIN*HIN + (h+1)*HIN + (w+1);
        float p2 = 0.f;
        for (int cp = q4; cp < 128; cp += 4) {
            float v0 = fb[(2*cp)*HIN*HIN];
            float v1 = fb[(2*cp+1)*HIN*HIN];
            p2 += v0*v0 + v1*v1;
            __half h0 = __float2half_rn(v0), h1 = __float2half_rn(v1);
            __half l0 = __float2half_rn(v0 - __half2float(h0));
            __half l1 = __float2half_rn(v1 - __half2float(h1));
            int jp = cp & 7, grp = cp >> 3;
            int phys = grp*16 + (((jp & 3) << 1) + (jp >> 2)) * 2;
            *(__half2*)&Ah[p*ASTR + phys] = __halves2half2(h0, h1);
            *(__half2*)&Al[p*ASTR + phys] = __halves2half2(l0, l1);
        }
        red[q4*64 + p] = p2;
    }
    __syncthreads();
    if (tid < 64) {
        f2s[tid]   = -alpha * (red[tid] + red[64+tid] + red[128+tid] + red[192+tid]);
        m_run[tid] = -1e30f;
        s_run[tid] = 0.f;
    }

    float acc[2][8][4];

    for (int s = 0; s < NSTAGE; ++s) {
        const int tile  = s >> 4;
        const int sub   = s & 15;
        const int chunk = sub >> 1;
        const int split = sub & 1;
        const __half* B = (s & 1) ? Bb1 : Bb0;

        asm volatile("cp.async.wait_group 0;" ::: "memory");
        __syncthreads();

        if (sub == 0) {
            #pragma unroll
            for (int mt = 0; mt < 2; ++mt)
                #pragma unroll
                for (int nt = 0; nt < 8; ++nt)
                    #pragma unroll
                    for (int i = 0; i < 4; ++i) acc[mt][nt][i] = 0.f;
            e2s[tid] = -alpha * g_e2[tile*BN + tid];
        }
        if (s + 1 < NSTAGE) issue(s + 1);

        // ---- mma: hi stage -> (Ah+Al)·Bhi sharing z; lo stage -> Ah·Blo ----
        const int kc = chunk * KC;
        #pragma unroll
        for (int g = 0; g < 2; ++g) {
            uint2 z[8];
            #pragma unroll
            for (int nt = 0; nt < 8; ++nt)
                z[nt] = *(const uint2*)&B[(wn*64 + nt*8 + tq)*BSTR + g*16 + 4*tr];

            unsigned afrH[2][4];
            #pragma unroll
            for (int mt = 0; mt < 2; ++mt) {
                int row = wm*32 + mt*16 + tq;
                uint2 x = *(const uint2*)&Ah[row*ASTR + kc + g*16 + 4*tr];
                uint2 y = *(const uint2*)&Ah[(row+8)*ASTR + kc + g*16 + 4*tr];
                afrH[mt][0] = x.x; afrH[mt][1] = y.x;
                afrH[mt][2] = x.y; afrH[mt][3] = y.y;
            }
            #pragma unroll
            for (int nt = 0; nt < 8; ++nt) {
                mma16816(acc[0][nt], afrH[0], z[nt].x, z[nt].y);
                mma16816(acc[1][nt], afrH[1], z[nt].x, z[nt].y);
            }
            if (split == 0) {
                unsigned afrL[2][4];
                #pragma unroll
                for (int mt = 0; mt < 2; ++mt) {
                    int row = wm*32 + mt*16 + tq;
                    uint2 x = *(const uint2*)&Al[row*ASTR + kc + g*16 + 4*tr];
                    uint2 y = *(const uint2*)&Al[(row+8)*ASTR + kc + g*16 + 4*tr];
                    afrL[mt][0] = x.x; afrL[mt][1] = y.x;
                    afrL[mt][2] = x.y; afrL[mt][3] = y.y;
                }
                #pragma unroll
                for (int nt = 0; nt < 8; ++nt) {
                    mma16816(acc[0][nt], afrL[0], z[nt].x, z[nt].y);
                    mma16816(acc[1][nt], afrL[1], z[nt].x, z[nt].y);
                }
            }
        }

        // ---- register epilogue at last chunk of tile ----
        if (sub == 15) {
            // logits into acc + per-row max over this warp's 64 codes
            float rmax[4];
            #pragma unroll
            for (int i = 0; i < 4; ++i) rmax[i] = -1e30f;
            #pragma unroll
            for (int mt = 0; mt < 2; ++mt) {
                int r0 = wm*32 + mt*16 + tq;
                float fa = f2s[r0], fb2 = f2s[r0 + 8];
                #pragma unroll
                for (int nt = 0; nt < 8; ++nt) {
                    int n0 = wn*64 + nt*8 + 2*tr;
                    float e0 = e2s[n0], e1 = e2s[n0 + 1];
                    float l0 = fmaf(alpha2, acc[mt][nt][0], fa  + e0);
                    float l1 = fmaf(alpha2, acc[mt][nt][1], fa  + e1);
                    float l2 = fmaf(alpha2, acc[mt][nt][2], fb2 + e0);
                    float l3 = fmaf(alpha2, acc[mt][nt][3], fb2 + e1);
                    acc[mt][nt][0] = l0; acc[mt][nt][1] = l1;
                    acc[mt][nt][2] = l2; acc[mt][nt][3] = l3;
                    rmax[2*mt]   = fmaxf(rmax[2*mt],   fmaxf(l0, l1));
                    rmax[2*mt+1] = fmaxf(rmax[2*mt+1], fmaxf(l2, l3));
                }
            }
            #pragma unroll
            for (int i = 0; i < 4; ++i) {
                rmax[i] = fmaxf(rmax[i], __shfl_xor_sync(0xffffffffu, rmax[i], 1));
                rmax[i] = fmaxf(rmax[i], __shfl_xor_sync(0xffffffffu, rmax[i], 2));
            }
            if (tr == 0) {
                #pragma unroll
                for (int i = 0; i < 4; ++i) {
                    int row = wm*32 + (i >> 1)*16 + tq + (i & 1)*8;
                    mpart[wn*64 + row] = rmax[i];
                }
            }
            __syncthreads();
            if (tid < 64) {
                float mm = fmaxf(fmaxf(mpart[tid], mpart[64 + tid]),
                                 fmaxf(mpart[128 + tid], mpart[192 + tid]));
                mnew[tid] = fmaxf(mm, m_run[tid]);
            }
            __syncthreads();

            // exp sums + direct logit stores
            float rsum[4];
            #pragma unroll
            for (int i = 0; i < 4; ++i) rsum[i] = 0.f;
            #pragma unroll
            for (int mt = 0; mt < 2; ++mt) {
                int r0 = wm*32 + mt*16 + tq;
                int r1 = r0 + 8;
                int gpa = gp0 + r0, gpb = gp0 + r1;
                int ba = gpa / PPB, bb2 = gpb / PPB;
                size_t base0 = (size_t)BOWOFF + (size_t)ba*NK*PPB + (gpa - ba*PPB);
                size_t base1 = (size_t)BOWOFF + (size_t)bb2*NK*PPB + (gpb - bb2*PPB);
                float mn0 = mnew[r0], mn1 = mnew[r1];
                #pragma unroll
                for (int nt = 0; nt < 8; ++nt) {
                    int ng = tile*BN + wn*64 + nt*8 + 2*tr;
                    float l0 = acc[mt][nt][0], l1 = acc[mt][nt][1];
                    float l2 = acc[mt][nt][2], l3 = acc[mt][nt][3];
                    rsum[2*mt]   += __expf(l0 - mn0) + __expf(l1 - mn0);
                    rsum[2*mt+1] += __expf(l2 - mn1) + __expf(l3 - mn1);
                    out[base0 + (size_t)ng*PPB]     = l0;
                    out[base0 + (size_t)(ng+1)*PPB] = l1;
                    out[base1 + (size_t)ng*PPB]     = l2;
                    out[base1 + (size_t)(ng+1)*PPB] = l3;
                }
            }
            #pragma unroll
            for (int i = 0; i < 4; ++i) {
                rsum[i] += __shfl_xor_sync(0xffffffffu, rsum[i], 1);
                rsum[i] += __shfl_xor_sync(0xffffffffu, rsum[i], 2);
            }
            if (tr == 0) {
                #pragma unroll
                for (int i = 0; i < 4; ++i) {
                    int row = wm*32 + (i >> 1)*16 + tq + (i & 1)*8;
                    spart[wn*64 + row] = rsum[i];
                }
            }
            __syncthreads();
            if (tid < 64) {
                float ss = spart[tid] + spart[64 + tid]
                         + spart[128 + tid] + spart[192 + tid];
                s_run[tid] = s_run[tid]*__expf(m_run[tid] - mnew[tid]) + ss;
                m_run[tid] = mnew[tid];
            }
        }
    }

    __syncthreads();
    if (tid < 64) {
        g_pixmax[gp0 + tid] = m_run[tid];
        g_pixsum[gp0 + tid] = s_run[tid];
    }
}

// ---------------------------------------------------------------------------
// Pass 2: codes = exp(l - m) / s (in place). One warp per code, 8 codes per
// block, no block syncs in the stream loop.
// ---------------------------------------------------------------------------
__global__ __launch_bounds__(256)
void pass2_kernel(float* __restrict__ out) {
    __shared__ __align__(16) float sm[PPB];
    __shared__ __align__(16) float ss[PPB];

    const int b  = blockIdx.x >> 8;          // 256 blocks per batch
    const int k0 = (blockIdx.x & 255) * 8;
    const int tid = threadIdx.x;

    const float* gm = g_pixmax + b*PPB;
    const float* gs = g_pixsum + b*PPB;
    for (int t = tid; t < PPB; t += 256) {
        sm[t] = gm[t];
        ss[t] = __frcp_rn(gs[t]);
    }
    __syncthreads();

    const int w = tid >> 5, lane = tid & 31;
    const int k = k0 + w;
    float4* p = reinterpret_cast<float4*>(out + (size_t)BOWOFF + ((size_t)(b*NK + k))*PPB);
    const float4* m4p = reinterpret_cast<const float4*>(sm);
    const float4* s4p = reinterpret_cast<const float4*>(ss);

    float acc = 0.f;
    #pragma unroll 2
    for (int t = lane; t < PPB/4; t += 32) {
        float4 v  = p[t];
        float4 m4 = m4p[t];
        float4 s4 = s4p[t];
        v.x = __expf(v.x - m4.x) * s4.x;
        v.y = __expf(v.y - m4.y) * s4.y;
        v.z = __expf(v.z - m4.z) * s4.z;
        v.w = __expf(v.w - m4.w) * s4.w;
        p[t] = v;
        acc += (v.x + v.y) + (v.z + v.w);
    }
    #pragma unroll
    for (int o = 16; o; o >>= 1) acc += __shfl_xor_sync(0xffffffffu, acc, o);
    if (lane == 0) g_bow[b*NK + k] = acc;
}

// ---------------------------------------------------------------------------
// Pass 3: bow normalize
// ---------------------------------------------------------------------------
__global__ __launch_bounds__(256)
void pass3_kernel(float* __restrict__ out) {
    __shared__ float redw[8];
    __shared__ float denom_s;
    int b   = blockIdx.x;
    int tid = threadIdx.x;
    const float invP = 1.0f / (float)PPB;

    float acc = 0.f;
    for (int k = tid; k < NK; k += 256) acc += g_bow[b*NK + k] * invP;
    #pragma unroll
    for (int o = 16; o; o >>= 1) acc += __shfl_xor_sync(0xffffffffu, acc, o);
    if ((tid & 31) == 0) redw[tid >> 5] = acc;
    __syncthreads();
    if (tid == 0) {
        float t = 0.f;
        #pragma unroll
        for (int i = 0; i < 8; i++) t += redw[i];
        denom_s = fmaxf(t, 1e-12f);
    }
    __syncthreads();
    float den = denom_s;
    for (int k = tid; k < NK; k += 256)
        out[b*NK + k] = (g_bow[b*NK + k] * invP) / den;
}

// ---------------------------------------------------------------------------
extern "C" void kernel_launch(void* const* d_in, const int* in_sizes, int n_in,
                              void* d_out, int out_size) {
    const float* feat = (const float*)d_in[0];   // (32,256,30,30)
    const float* emb  = (const float*)d_in[1];   // (2048,256)
    const float* md   = (const float*)d_in[2];   // (1,)
    float* out = (float*)d_out;

    cudaFuncSetAttribute(pass1_kernel,
                         cudaFuncAttributeMaxDynamicSharedMemorySize, SMEM1_BYTES);

    e2_kernel   <<<NK/8, 256>>>(emb);
    split_kernel<<<NK*CC/2/256, 256>>>(emb);
    pass1_kernel<<<NPIX/BM, 256, SMEM1_BYTES>>>(feat, md, out);
    pass2_kernel<<<BB*NK/8, 256>>>(out);
    pass3_kernel<<<BB, 256>>>(out);
    (void)in_sizes; (void)n_in; (void)out_size;
}

// round 7
// speedup vs baseline: 2.8097x; 1.0179x over previous
#include <cuda_runtime.h>
#include <cuda_fp16.h>
#include <math.h>

// Problem constants
#define BB   32
#define CC   256
#define HIN  30
#define OH   28
#define PPB  784
#define NPIX 25088
#define NK   2048
#define BOWOFF (BB*NK)

// Pass-1 tiling (tensor-core)
#define BM 64              // pixels per block
#define BN 256             // codes per tile
#define KC 16              // k-chunk (halves)
#define NTILE (NK/BN)      // 8
#define NSTAGE (NTILE*32)  // 256 stages: 16 chunks x {hi,lo} per tile
#define ASTR 272           // A smem row stride (halves)
#define BSTR 16            // B smem row stride (halves) — 32B rows, conflict-free
#define SLOT_HALVES (BN*BSTR)   // 4096 halves = 8KB per slot

// smem byte offsets (total ~104 KB -> 2 blocks/SM)
#define OFF_AL   34816
#define OFF_B    69632          // 4 slots x 8KB = 32KB
#define OFF_F2   102400
#define OFF_E2   102656
#define OFF_MN   103680
#define OFF_MR   103936
#define OFF_SR   104192
#define OFF_MP   104448
#define OFF_SP   105472
#define SMEM1_BYTES 106496

// Scratch
__device__ float g_e2[NK];
__device__ float g_pixmax[NPIX];
__device__ float g_pixsum[NPIX];
__device__ float g_mtile[NTILE*NPIX];
__device__ float g_bow[BB*NK];
__device__ __align__(16) __half g_ehiP[NK*CC];  // k-permuted fp16 hi split
__device__ __align__(16) __half g_eloP[NK*CC];  // k-permuted fp16 lo split

// ---------------------------------------------------------------------------
__device__ __forceinline__ void mma16816(float* c, const unsigned* a,
                                         unsigned b0, unsigned b1) {
    asm volatile(
        "mma.sync.aligned.m16n8k16.row.col.f32.f16.f16.f32 "
        "{%0,%1,%2,%3}, {%4,%5,%6,%7}, {%8,%9}, {%0,%1,%2,%3};"
        : "+f"(c[0]), "+f"(c[1]), "+f"(c[2]), "+f"(c[3])
        : "r"(a[0]), "r"(a[1]), "r"(a[2]), "r"(a[3]), "r"(b0), "r"(b1));
}

// ---------------------------------------------------------------------------
// Prep: fused e2 + fp16 hi/lo split (k-permuted). Block = 2 codebook rows.
// ---------------------------------------------------------------------------
__global__ __launch_bounds__(256)
void prep_kernel(const float* __restrict__ emb) {
    __shared__ float red[8];
    const int tid = threadIdx.x;
    const int idx = blockIdx.x * 256 + tid;       // pair index
    const int k  = idx >> 7;
    const int cp = idx & 127;
    float v0 = emb[k*CC + 2*cp];
    float v1 = emb[k*CC + 2*cp + 1];
    __half h0 = __float2half_rn(v0), h1 = __float2half_rn(v1);
    __half l0 = __float2half_rn(v0 - __half2float(h0));
    __half l1 = __float2half_rn(v1 - __half2float(h1));
    int jp = cp & 7, grp = cp >> 3;
    int phys = grp*16 + (((jp & 3) << 1) + (jp >> 2)) * 2;
    *(__half2*)&g_ehiP[(size_t)k*CC + phys] = __halves2half2(h0, h1);
    *(__half2*)&g_eloP[(size_t)k*CC + phys] = __halves2half2(l0, l1);

    float p2 = v0*v0 + v1*v1;
    #pragma unroll
    for (int o = 16; o; o >>= 1) p2 += __shfl_xor_sync(0xffffffffu, p2, o);
    if ((tid & 31) == 0) red[tid >> 5] = p2;
    __syncthreads();
    if ((tid & 127) == 0) {
        int w0 = (tid >> 7) * 4;
        g_e2[k] = red[w0] + red[w0+1] + red[w0+2] + red[w0+3];
    }
}

// ---------------------------------------------------------------------------
// Pass 1: 64 pixels x all 2048 codes, fp16-split HMMA, occ=2.
// 4-slot cp.async ring, prefetch distance 3 (one commit group per stage).
// Epilogue stores exp(l - m_tile) and records m_tile; pass2 rescales.
// ---------------------------------------------------------------------------
extern __shared__ float smem1[];

__global__ __launch_bounds__(256, 2)
void pass1_kernel(const float* __restrict__ feat,
                  const float* __restrict__ md,
                  float* __restrict__ out)
{
    char* smem_raw = (char*)smem1;
    __half* Ah    = (__half*)smem_raw;               // [64][272]
    __half* Al    = (__half*)(smem_raw + OFF_AL);    // [64][272]
    __half* Bbuf  = (__half*)(smem_raw + OFF_B);     // 4 x [256][16]
    float*  f2s   = (float*)(smem_raw + OFF_F2);     // 64
    float*  e2s   = (float*)(smem_raw + OFF_E2);     // 256
    float*  mnew  = (float*)(smem_raw + OFF_MN);     // 64
    float*  m_run = (float*)(smem_raw + OFF_MR);     // 64
    float*  s_run = (float*)(smem_raw + OFF_SR);     // 64
    float*  mpart = (float*)(smem_raw + OFF_MP);     // 4 x 64
    float*  spart = (float*)(smem_raw + OFF_SP);     // 4 x 64
    float*  red   = mpart;                           // alias (prologue only)

    const int tid  = threadIdx.x;
    const int warp = tid >> 5;
    const int lane = tid & 31;
    const int wm = warp >> 2;        // 0..1
    const int wn = warp & 3;         // 0..3
    const int tq = lane >> 2;        // 0..7
    const int tr = lane & 3;         // 0..3
    const int gp0 = blockIdx.x * BM;
    const float alpha  = 15.0f / md[0];
    const float alpha2 = 2.0f * alpha;

    // ---- one 8KB B chunk via cp.async (2 x 16B per thread) ----
    auto issue = [&](int s) {
        int tile = s >> 5, sub = s & 31;
        int chunk = sub >> 1, split = sub & 1;
        const __half* src = (split ? g_eloP : g_ehiP)
                          + (size_t)tile*BN*CC + chunk*KC;
        __half* dstB = Bbuf + (size_t)(s & 3)*SLOT_HALVES;
        #pragma unroll
        for (int it = 0; it < 2; ++it) {
            int lin = it*256 + tid;
            int row = lin >> 1, seg = lin & 1;
            const __half* sp = src + (size_t)row*CC + seg*8;
            unsigned d = (unsigned)__cvta_generic_to_shared(dstB + row*BSTR + seg*8);
            asm volatile("cp.async.cg.shared.global [%0], [%1], 16;"
                         :: "r"(d), "l"(sp) : "memory");
        }
        asm volatile("cp.async.commit_group;" ::: "memory");
    };

    issue(0); issue(1); issue(2);   // prefetch distance 3

    // ---- load + split features, accumulate f2 ----
    {
        int p  = tid & 63;
        int q4 = tid >> 6;
        int gp = gp0 + p;
        int b  = gp / PPB;
        int r  = gp - b*PPB;
        int h  = r / OH, w = r - h*OH;
        const float* fb = feat + (size_t)b*CC*HIN*HIN + (h+1)*HIN + (w+1);
        float p2 = 0.f;
        for (int cp = q4; cp < 128; cp += 4) {
            float v0 = fb[(2*cp)*HIN*HIN];
            float v1 = fb[(2*cp+1)*HIN*HIN];
            p2 += v0*v0 + v1*v1;
            __half h0 = __float2half_rn(v0), h1 = __float2half_rn(v1);
            __half l0 = __float2half_rn(v0 - __half2float(h0));
            __half l1 = __float2half_rn(v1 - __half2float(h1));
            int jp = cp & 7, grp = cp >> 3;
            int phys = grp*16 + (((jp & 3) << 1) + (jp >> 2)) * 2;
            *(__half2*)&Ah[p*ASTR + phys] = __halves2half2(h0, h1);
            *(__half2*)&Al[p*ASTR + phys] = __halves2half2(l0, l1);
        }
        red[q4*64 + p] = p2;
    }
    __syncthreads();
    if (tid < 64) {
        f2s[tid]   = -alpha * (red[tid] + red[64+tid] + red[128+tid] + red[192+tid]);
        m_run[tid] = -1e30f;
        s_run[tid] = 0.f;
    }

    float acc[2][8][4];

    for (int s = 0; s < NSTAGE; ++s) {
        const int tile  = s >> 5;
        const int sub   = s & 31;
        const int chunk = sub >> 1;
        const int split = sub & 1;

        asm volatile("cp.async.wait_group 2;" ::: "memory");
        __syncthreads();

        if (sub == 0) {
            #pragma unroll
            for (int mt = 0; mt < 2; ++mt)
                #pragma unroll
                for (int nt = 0; nt < 8; ++nt)
                    #pragma unroll
                    for (int i = 0; i < 4; ++i) acc[mt][nt][i] = 0.f;
            e2s[tid] = -alpha * g_e2[tile*BN + tid];
        }
        if (s + 3 < NSTAGE) issue(s + 3);
        else asm volatile("cp.async.commit_group;" ::: "memory");

        // ---- mma on slot s&3: hi -> (Ah+Al)·Bhi shared z; lo -> Ah·Blo ----
        const __half* B = Bbuf + (size_t)(s & 3)*SLOT_HALVES;
        const int kc = chunk * KC;
        {
            uint2 z[8];
            #pragma unroll
            for (int nt = 0; nt < 8; ++nt)
                z[nt] = *(const uint2*)&B[(wn*64 + nt*8 + tq)*BSTR + 4*tr];

            unsigned afrH[2][4];
            #pragma unroll
            for (int mt = 0; mt < 2; ++mt) {
                int row = wm*32 + mt*16 + tq;
                uint2 x = *(const uint2*)&Ah[row*ASTR + kc + 4*tr];
                uint2 y = *(const uint2*)&Ah[(row+8)*ASTR + kc + 4*tr];
                afrH[mt][0] = x.x; afrH[mt][1] = y.x;
                afrH[mt][2] = x.y; afrH[mt][3] = y.y;
            }
            #pragma unroll
            for (int nt = 0; nt < 8; ++nt) {
                mma16816(acc[0][nt], afrH[0], z[nt].x, z[nt].y);
                mma16816(acc[1][nt], afrH[1], z[nt].x, z[nt].y);
            }
            if (split == 0) {
                unsigned afrL[2][4];
                #pragma unroll
                for (int mt = 0; mt < 2; ++mt) {
                    int row = wm*32 + mt*16 + tq;
                    uint2 x = *(const uint2*)&Al[row*ASTR + kc + 4*tr];
                    uint2 y = *(const uint2*)&Al[(row+8)*ASTR + kc + 4*tr];
                    afrL[mt][0] = x.x; afrL[mt][1] = y.x;
                    afrL[mt][2] = x.y; afrL[mt][3] = y.y;
                }
                #pragma unroll
                for (int nt = 0; nt < 8; ++nt) {
                    mma16816(acc[0][nt], afrL[0], z[nt].x, z[nt].y);
                    mma16816(acc[1][nt], afrL[1], z[nt].x, z[nt].y);
                }
            }
        }

        // ---- register epilogue at last chunk of tile ----
        if (sub == 31) {
            float rmax[4];
            #pragma unroll
            for (int i = 0; i < 4; ++i) rmax[i] = -1e30f;
            #pragma unroll
            for (int mt = 0; mt < 2; ++mt) {
                int r0 = wm*32 + mt*16 + tq;
                float fa = f2s[r0], fb2 = f2s[r0 + 8];
                #pragma unroll
                for (int nt = 0; nt < 8; ++nt) {
                    int n0 = wn*64 + nt*8 + 2*tr;
                    float e0 = e2s[n0], e1 = e2s[n0 + 1];
                    float l0 = fmaf(alpha2, acc[mt][nt][0], fa  + e0);
                    float l1 = fmaf(alpha2, acc[mt][nt][1], fa  + e1);
                    float l2 = fmaf(alpha2, acc[mt][nt][2], fb2 + e0);
                    float l3 = fmaf(alpha2, acc[mt][nt][3], fb2 + e1);
                    acc[mt][nt][0] = l0; acc[mt][nt][1] = l1;
                    acc[mt][nt][2] = l2; acc[mt][nt][3] = l3;
                    rmax[2*mt]   = fmaxf(rmax[2*mt],   fmaxf(l0, l1));
                    rmax[2*mt+1] = fmaxf(rmax[2*mt+1], fmaxf(l2, l3));
                }
            }
            #pragma unroll
            for (int i = 0; i < 4; ++i) {
                rmax[i] = fmaxf(rmax[i], __shfl_xor_sync(0xffffffffu, rmax[i], 1));
                rmax[i] = fmaxf(rmax[i], __shfl_xor_sync(0xffffffffu, rmax[i], 2));
            }
            if (tr == 0) {
                #pragma unroll
                for (int i = 0; i < 4; ++i) {
                    int row = wm*32 + (i >> 1)*16 + tq + (i & 1)*8;
                    mpart[wn*64 + row] = rmax[i];
                }
            }
            __syncthreads();
            if (tid < 64) {
                float mm = fmaxf(fmaxf(mpart[tid], mpart[64 + tid]),
                                 fmaxf(mpart[128 + tid], mpart[192 + tid]));
                mnew[tid] = fmaxf(mm, m_run[tid]);
            }
            __syncthreads();

            // exp sums + store exp(l - m_tile) directly
            float rsum[4];
            #pragma unroll
            for (int i = 0; i < 4; ++i) rsum[i] = 0.f;
            #pragma unroll
            for (int mt = 0; mt < 2; ++mt) {
                int r0 = wm*32 + mt*16 + tq;
                int r1 = r0 + 8;
                int gpa = gp0 + r0, gpb = gp0 + r1;
                int ba = gpa / PPB, bb2 = gpb / PPB;
                size_t base0 = (size_t)BOWOFF + (size_t)ba*NK*PPB + (gpa - ba*PPB);
                size_t base1 = (size_t)BOWOFF + (size_t)bb2*NK*PPB + (gpb - bb2*PPB);
                float mn0 = mnew[r0], mn1 = mnew[r1];
                #pragma unroll
                for (int nt = 0; nt < 8; ++nt) {
                    int ng = tile*BN + wn*64 + nt*8 + 2*tr;
                    float e00 = __expf(acc[mt][nt][0] - mn0);
                    float e01 = __expf(acc[mt][nt][1] - mn0);
                    float e10 = __expf(acc[mt][nt][2] - mn1);
                    float e11 = __expf(acc[mt][nt][3] - mn1);
                    rsum[2*mt]   += e00 + e01;
                    rsum[2*mt+1] += e10 + e11;
                    out[base0 + (size_t)ng*PPB]     = e00;
                    out[base0 + (size_t)(ng+1)*PPB] = e01;
                    out[base1 + (size_t)ng*PPB]     = e10;
                    out[base1 + (size_t)(ng+1)*PPB] = e11;
                }
            }
            #pragma unroll
            for (int i = 0; i < 4; ++i) {
                rsum[i] += __shfl_xor_sync(0xffffffffu, rsum[i], 1);
                rsum[i] += __shfl_xor_sync(0xffffffffu, rsum[i], 2);
            }
            if (tr == 0) {
                #pragma unroll
                for (int i = 0; i < 4; ++i) {
                    int row = wm*32 + (i >> 1)*16 + tq + (i & 1)*8;
                    spart[wn*64 + row] = rsum[i];
                }
            }
            __syncthreads();
            if (tid < 64) {
                float ss = spart[tid] + spart[64 + tid]
                         + spart[128 + tid] + spart[192 + tid];
                s_run[tid] = s_run[tid]*__expf(m_run[tid] - mnew[tid]) + ss;
                m_run[tid] = mnew[tid];
                g_mtile[tile*NPIX + gp0 + tid] = mnew[tid];
            }
        }
    }

    __syncthreads();
    if (tid < 64) {
        g_pixmax[gp0 + tid] = m_run[tid];
        g_pixsum[gp0 + tid] = s_run[tid];
    }
}

// ---------------------------------------------------------------------------
// Pass 2: codes *= exp(m_tile - m_fin)/s  (pure FMA + memory; no per-element
// exp). One warp per code, 8 codes (same tile) per block.
// ---------------------------------------------------------------------------
__global__ __launch_bounds__(256)
void pass2_kernel(float* __restrict__ out) {
    __shared__ __align__(16) float fac[PPB];

    const int b   = blockIdx.x >> 8;          // 256 blocks per batch
    const int k0  = (blockIdx.x & 255) * 8;
    const int tile = k0 >> 8;
    const int tid = threadIdx.x;

    for (int t = tid; t < PPB; t += 256) {
        float mt = g_mtile[tile*NPIX + b*PPB + t];
        float mf = g_pixmax[b*PPB + t];
        float sf = g_pixsum[b*PPB + t];
        fac[t] = __expf(mt - mf) * __frcp_rn(sf);
    }
    __syncthreads();

    const int w = tid >> 5, lane = tid & 31;
    const int k = k0 + w;
    float4* p = reinterpret_cast<float4*>(out + (size_t)BOWOFF + ((size_t)(b*NK + k))*PPB);
    const float4* f4p = reinterpret_cast<const float4*>(fac);

    float acc = 0.f;
    #pragma unroll 2
    for (int t = lane; t < PPB/4; t += 32) {
        float4 v  = p[t];
        float4 f4 = f4p[t];
        v.x *= f4.x; v.y *= f4.y; v.z *= f4.z; v.w *= f4.w;
        p[t] = v;
        acc += (v.x + v.y) + (v.z + v.w);
    }
    #pragma unroll
    for (int o = 16; o; o >>= 1) acc += __shfl_xor_sync(0xffffffffu, acc, o);
    if (lane == 0) g_bow[b*NK + k] = acc;
}

// ---------------------------------------------------------------------------
// Pass 3: bow normalize
// ---------------------------------------------------------------------------
__global__ __launch_bounds__(256)
void pass3_kernel(float* __restrict__ out) {
    __shared__ float redw[8];
    __shared__ float denom_s;
    int b   = blockIdx.x;
    int tid = threadIdx.x;
    const float invP = 1.0f / (float)PPB;

    float acc = 0.f;
    for (int k = tid; k < NK; k += 256) acc += g_bow[b*NK + k] * invP;
    #pragma unroll
    for (int o = 16; o; o >>= 1) acc += __shfl_xor_sync(0xffffffffu, acc, o);
    if ((tid & 31) == 0) redw[tid >> 5] = acc;
    __syncthreads();
    if (tid == 0) {
        float t = 0.f;
        #pragma unroll
        for (int i = 0; i < 8; i++) t += redw[i];
        denom_s = fmaxf(t, 1e-12f);
    }
    __syncthreads();
    float den = denom_s;
    for (int k = tid; k < NK; k += 256)
        out[b*NK + k] = (g_bow[b*NK + k] * invP) / den;
}

// ---------------------------------------------------------------------------
extern "C" void kernel_launch(void* const* d_in, const int* in_sizes, int n_in,
                              void* d_out, int out_size) {
    const float* feat = (const float*)d_in[0];   // (32,256,30,30)
    const float* emb  = (const float*)d_in[1];   // (2048,256)
    const float* md   = (const float*)d_in[2];   // (1,)
    float* out = (float*)d_out;

    cudaFuncSetAttribute(pass1_kernel,
                         cudaFuncAttributeMaxDynamicSharedMemorySize, SMEM1_BYTES);

    prep_kernel <<<NK/2, 256>>>(emb);
    pass1_kernel<<<NPIX/BM, 256, SMEM1_BYTES>>>(feat, md, out);
    pass2_kernel<<<BB*NK/8, 256>>>(out);
    pass3_kernel<<<BB, 256>>>(out);
    (void)in_sizes; (void)n_in; (void)out_size;
}

// round 8
// speedup vs baseline: 2.8919x; 1.0293x over previous
#include <cuda_runtime.h>
#include <cuda_fp16.h>
#include <math.h>

// Problem constants
#define BB   32
#define CC   256
#define HIN  30
#define OH   28
#define PPB  784
#define NPIX 25088
#define NK   2048
#define BOWOFF (BB*NK)

// Pass-1 tiling (tensor-core)
#define BM 64              // pixels per block
#define BN 256             // codes per tile
#define KC 16              // k-chunk (halves)
#define NTILE 8            // global code tiles
#define HTILE 4            // tiles per half-block
#define NSTAGE (HTILE*32)  // 128 stages per block: 16 chunks x {hi,lo} per tile
#define ASTR 272           // A smem row stride (halves)
#define BSTR 16            // B smem row stride (halves) — 32B rows, conflict-free
#define SLOT_HALVES (BN*BSTR)   // 4096 halves = 8KB per slot

// smem byte offsets (total ~104 KB -> 2 blocks/SM)
#define OFF_AL   34816
#define OFF_B    69632          // 4 slots x 8KB = 32KB
#define OFF_F2   102400
#define OFF_E2   102656
#define OFF_MN   103680
#define OFF_MR   103936
#define OFF_SR   104192
#define OFF_MP   104448
#define OFF_SP   105472
#define SMEM1_BYTES 106496

// Scratch
__device__ float g_e2[NK];
__device__ float g_pixmax[2*NPIX];   // [half][pix]
__device__ float g_pixsum[2*NPIX];
__device__ float g_mtile[NTILE*NPIX];
__device__ float g_bow[BB*NK];
__device__ __align__(16) __half g_ehiP[NK*CC];  // k-permuted fp16 hi split
__device__ __align__(16) __half g_eloP[NK*CC];  // k-permuted fp16 lo split

// ---------------------------------------------------------------------------
__device__ __forceinline__ void mma16816(float* c, const unsigned* a,
                                         unsigned b0, unsigned b1) {
    asm volatile(
        "mma.sync.aligned.m16n8k16.row.col.f32.f16.f16.f32 "
        "{%0,%1,%2,%3}, {%4,%5,%6,%7}, {%8,%9}, {%0,%1,%2,%3};"
        : "+f"(c[0]), "+f"(c[1]), "+f"(c[2]), "+f"(c[3])
        : "r"(a[0]), "r"(a[1]), "r"(a[2]), "r"(a[3]), "r"(b0), "r"(b1));
}

// ---------------------------------------------------------------------------
// Prep: fused e2 + fp16 hi/lo split (k-permuted). Block = 2 codebook rows.
// ---------------------------------------------------------------------------
__global__ __launch_bounds__(256)
void prep_kernel(const float* __restrict__ emb) {
    __shared__ float red[8];
    const int tid = threadIdx.x;
    const int idx = blockIdx.x * 256 + tid;       // pair index
    const int k  = idx >> 7;
    const int cp = idx & 127;
    float v0 = emb[k*CC + 2*cp];
    float v1 = emb[k*CC + 2*cp + 1];
    __half h0 = __float2half_rn(v0), h1 = __float2half_rn(v1);
    __half l0 = __float2half_rn(v0 - __half2float(h0));
    __half l1 = __float2half_rn(v1 - __half2float(h1));
    int jp = cp & 7, grp = cp >> 3;
    int phys = grp*16 + (((jp & 3) << 1) + (jp >> 2)) * 2;
    *(__half2*)&g_ehiP[(size_t)k*CC + phys] = __halves2half2(h0, h1);
    *(__half2*)&g_eloP[(size_t)k*CC + phys] = __halves2half2(l0, l1);

    float p2 = v0*v0 + v1*v1;
    #pragma unroll
    for (int o = 16; o; o >>= 1) p2 += __shfl_xor_sync(0xffffffffu, p2, o);
    if ((tid & 31) == 0) red[tid >> 5] = p2;
    __syncthreads();
    if ((tid & 127) == 0) {
        int w0 = (tid >> 7) * 4;
        g_e2[k] = red[w0] + red[w0+1] + red[w0+2] + red[w0+3];
    }
}

// ---------------------------------------------------------------------------
// Pass 1: 64 pixels x 1024 codes (half the codebook) per block; 784 blocks.
// fp16-split HMMA, occ=2, 4-slot cp.async ring (prefetch distance 3).
// Epilogue stores exp(l - m_tile), records m_tile; per-half (m,s) to global.
// ---------------------------------------------------------------------------
extern __shared__ float smem1[];

__global__ __launch_bounds__(256, 2)
void pass1_kernel(const float* __restrict__ feat,
                  const float* __restrict__ md,
                  float* __restrict__ out)
{
    char* smem_raw = (char*)smem1;
    __half* Ah    = (__half*)smem_raw;               // [64][272]
    __half* Al    = (__half*)(smem_raw + OFF_AL);    // [64][272]
    __half* Bbuf  = (__half*)(smem_raw + OFF_B);     // 4 x [256][16]
    float*  f2s   = (float*)(smem_raw + OFF_F2);     // 64
    float*  e2s   = (float*)(smem_raw + OFF_E2);     // 256
    float*  mnew  = (float*)(smem_raw + OFF_MN);     // 64
    float*  m_run = (float*)(smem_raw + OFF_MR);     // 64
    float*  s_run = (float*)(smem_raw + OFF_SR);     // 64
    float*  mpart = (float*)(smem_raw + OFF_MP);     // 4 x 64
    float*  spart = (float*)(smem_raw + OFF_SP);     // 4 x 64
    float*  red   = mpart;                           // alias (prologue only)

    const int tid  = threadIdx.x;
    const int warp = tid >> 5;
    const int lane = tid & 31;
    const int wm = warp >> 2;        // 0..1
    const int wn = warp & 3;         // 0..3
    const int tq = lane >> 2;        // 0..7
    const int tr = lane & 3;         // 0..3
    const int half = blockIdx.x & 1;
    const int gp0  = (blockIdx.x >> 1) * BM;
    const int tileBase = half * HTILE;
    const float alpha  = 15.0f / md[0];
    const float alpha2 = 2.0f * alpha;

    // ---- one 8KB B chunk via cp.async (2 x 16B per thread) ----
    auto issue = [&](int s) {
        int tile = tileBase + (s >> 5), sub = s & 31;
        int chunk = sub >> 1, split = sub & 1;
        const __half* src = (split ? g_eloP : g_ehiP)
                          + (size_t)tile*BN*CC + chunk*KC;
        __half* dstB = Bbuf + (size_t)(s & 3)*SLOT_HALVES;
        #pragma unroll
        for (int it = 0; it < 2; ++it) {
            int lin = it*256 + tid;
            int row = lin >> 1, seg = lin & 1;
            const __half* sp = src + (size_t)row*CC + seg*8;
            unsigned d = (unsigned)__cvta_generic_to_shared(dstB + row*BSTR + seg*8);
            asm volatile("cp.async.cg.shared.global [%0], [%1], 16;"
                         :: "r"(d), "l"(sp) : "memory");
        }
        asm volatile("cp.async.commit_group;" ::: "memory");
    };

    issue(0); issue(1); issue(2);   // prefetch distance 3

    // ---- load + split features, accumulate f2 ----
    {
        int p  = tid & 63;
        int q4 = tid >> 6;
        int gp = gp0 + p;
        int b  = gp / PPB;
        int r  = gp - b*PPB;
        int h  = r / OH, w = r - h*OH;
        const float* fb = feat + (size_t)b*CC*HIN*HIN + (h+1)*HIN + (w+1);
        float p2 = 0.f;
        for (int cp = q4; cp < 128; cp += 4) {
            float v0 = fb[(2*cp)*HIN*HIN];
            float v1 = fb[(2*cp+1)*HIN*HIN];
            p2 += v0*v0 + v1*v1;
            __half h0 = __float2half_rn(v0), h1 = __float2half_rn(v1);
            __half l0 = __float2half_rn(v0 - __half2float(h0));
            __half l1 = __float2half_rn(v1 - __half2float(h1));
            int jp = cp & 7, grp = cp >> 3;
            int phys = grp*16 + (((jp & 3) << 1) + (jp >> 2)) * 2;
            *(__half2*)&Ah[p*ASTR + phys] = __halves2half2(h0, h1);
            *(__half2*)&Al[p*ASTR + phys] = __halves2half2(l0, l1);
        }
        red[q4*64 + p] = p2;
    }
    __syncthreads();
    if (tid < 64) {
        f2s[tid]   = -alpha * (red[tid] + red[64+tid] + red[128+tid] + red[192+tid]);
        m_run[tid] = -1e30f;
        s_run[tid] = 0.f;
    }

    float acc[2][8][4];

    for (int s = 0; s < NSTAGE; ++s) {
        const int tile  = tileBase + (s >> 5);
        const int sub   = s & 31;
        const int chunk = sub >> 1;
        const int split = sub & 1;

        asm volatile("cp.async.wait_group 2;" ::: "memory");
        __syncthreads();

        if (sub == 0) {
            #pragma unroll
            for (int mt = 0; mt < 2; ++mt)
                #pragma unroll
                for (int nt = 0; nt < 8; ++nt)
                    #pragma unroll
                    for (int i = 0; i < 4; ++i) acc[mt][nt][i] = 0.f;
            e2s[tid] = -alpha * g_e2[tile*BN + tid];
        }
        if (s + 3 < NSTAGE) issue(s + 3);
        else asm volatile("cp.async.commit_group;" ::: "memory");

        // ---- mma on slot s&3: hi -> (Ah+Al)·Bhi shared z; lo -> Ah·Blo ----
        const __half* B = Bbuf + (size_t)(s & 3)*SLOT_HALVES;
        const int kc = chunk * KC;
        {
            uint2 z[8];
            #pragma unroll
            for (int nt = 0; nt < 8; ++nt)
                z[nt] = *(const uint2*)&B[(wn*64 + nt*8 + tq)*BSTR + 4*tr];

            unsigned afrH[2][4];
            #pragma unroll
            for (int mt = 0; mt < 2; ++mt) {
                int row = wm*32 + mt*16 + tq;
                uint2 x = *(const uint2*)&Ah[row*ASTR + kc + 4*tr];
                uint2 y = *(const uint2*)&Ah[(row+8)*ASTR + kc + 4*tr];
                afrH[mt][0] = x.x; afrH[mt][1] = y.x;
                afrH[mt][2] = x.y; afrH[mt][3] = y.y;
            }
            #pragma unroll
            for (int nt = 0; nt < 8; ++nt) {
                mma16816(acc[0][nt], afrH[0], z[nt].x, z[nt].y);
                mma16816(acc[1][nt], afrH[1], z[nt].x, z[nt].y);
            }
            if (split == 0) {
                unsigned afrL[2][4];
                #pragma unroll
                for (int mt = 0; mt < 2; ++mt) {
                    int row = wm*32 + mt*16 + tq;
                    uint2 x = *(const uint2*)&Al[row*ASTR + kc + 4*tr];
                    uint2 y = *(const uint2*)&Al[(row+8)*ASTR + kc + 4*tr];
                    afrL[mt][0] = x.x; afrL[mt][1] = y.x;
                    afrL[mt][2] = x.y; afrL[mt][3] = y.y;
                }
                #pragma unroll
                for (int nt = 0; nt < 8; ++nt) {
                    mma16816(acc[0][nt], afrL[0], z[nt].x, z[nt].y);
                    mma16816(acc[1][nt], afrL[1], z[nt].x, z[nt].y);
                }
            }
        }

        // ---- register epilogue at last chunk of tile ----
        if (sub == 31) {
            float rmax[4];
            #pragma unroll
            for (int i = 0; i < 4; ++i) rmax[i] = -1e30f;
            #pragma unroll
            for (int mt = 0; mt < 2; ++mt) {
                int r0 = wm*32 + mt*16 + tq;
                float fa = f2s[r0], fb2 = f2s[r0 + 8];
                #pragma unroll
                for (int nt = 0; nt < 8; ++nt) {
                    int n0 = wn*64 + nt*8 + 2*tr;
                    float e0 = e2s[n0], e1 = e2s[n0 + 1];
                    float l0 = fmaf(alpha2, acc[mt][nt][0], fa  + e0);
                    float l1 = fmaf(alpha2, acc[mt][nt][1], fa  + e1);
                    float l2 = fmaf(alpha2, acc[mt][nt][2], fb2 + e0);
                    float l3 = fmaf(alpha2, acc[mt][nt][3], fb2 + e1);
                    acc[mt][nt][0] = l0; acc[mt][nt][1] = l1;
                    acc[mt][nt][2] = l2; acc[mt][nt][3] = l3;
                    rmax[2*mt]   = fmaxf(rmax[2*mt],   fmaxf(l0, l1));
                    rmax[2*mt+1] = fmaxf(rmax[2*mt+1], fmaxf(l2, l3));
                }
            }
            #pragma unroll
            for (int i = 0; i < 4; ++i) {
                rmax[i] = fmaxf(rmax[i], __shfl_xor_sync(0xffffffffu, rmax[i], 1));
                rmax[i] = fmaxf(rmax[i], __shfl_xor_sync(0xffffffffu, rmax[i], 2));
            }
            if (tr == 0) {
                #pragma unroll
                for (int i = 0; i < 4; ++i) {
                    int row = wm*32 + (i >> 1)*16 + tq + (i & 1)*8;
                    mpart[wn*64 + row] = rmax[i];
                }
            }
            __syncthreads();
            if (tid < 64) {
                float mm = fmaxf(fmaxf(mpart[tid], mpart[64 + tid]),
                                 fmaxf(mpart[128 + tid], mpart[192 + tid]));
                mnew[tid] = fmaxf(mm, m_run[tid]);
            }
            __syncthreads();

            // exp sums + store exp(l - m_tile) directly
            float rsum[4];
            #pragma unroll
            for (int i = 0; i < 4; ++i) rsum[i] = 0.f;
            #pragma unroll
            for (int mt = 0; mt < 2; ++mt) {
                int r0 = wm*32 + mt*16 + tq;
                int r1 = r0 + 8;
                int gpa = gp0 + r0, gpb = gp0 + r1;
                int ba = gpa / PPB, bb2 = gpb / PPB;
                size_t base0 = (size_t)BOWOFF + (size_t)ba*NK*PPB + (gpa - ba*PPB);
                size_t base1 = (size_t)BOWOFF + (size_t)bb2*NK*PPB + (gpb - bb2*PPB);
                float mn0 = mnew[r0], mn1 = mnew[r1];
                #pragma unroll
                for (int nt = 0; nt < 8; ++nt) {
                    int ng = tile*BN + wn*64 + nt*8 + 2*tr;
                    float e00 = __expf(acc[mt][nt][0] - mn0);
                    float e01 = __expf(acc[mt][nt][1] - mn0);
                    float e10 = __expf(acc[mt][nt][2] - mn1);
                    float e11 = __expf(acc[mt][nt][3] - mn1);
                    rsum[2*mt]   += e00 + e01;
                    rsum[2*mt+1] += e10 + e11;
                    out[base0 + (size_t)ng*PPB]     = e00;
                    out[base0 + (size_t)(ng+1)*PPB] = e01;
                    out[base1 + (size_t)ng*PPB]     = e10;
                    out[base1 + (size_t)(ng+1)*PPB] = e11;
                }
            }
            #pragma unroll
            for (int i = 0; i < 4; ++i) {
                rsum[i] += __shfl_xor_sync(0xffffffffu, rsum[i], 1);
                rsum[i] += __shfl_xor_sync(0xffffffffu, rsum[i], 2);
            }
            if (tr == 0) {
                #pragma unroll
                for (int i = 0; i < 4; ++i) {
                    int row = wm*32 + (i >> 1)*16 + tq + (i & 1)*8;
                    spart[wn*64 + row] = rsum[i];
                }
            }
            __syncthreads();
            if (tid < 64) {
                float ss = spart[tid] + spart[64 + tid]
                         + spart[128 + tid] + spart[192 + tid];
                s_run[tid] = s_run[tid]*__expf(m_run[tid] - mnew[tid]) + ss;
                m_run[tid] = mnew[tid];
                g_mtile[tile*NPIX + gp0 + tid] = mnew[tid];
            }
        }
    }

    __syncthreads();
    if (tid < 64) {
        g_pixmax[half*NPIX + gp0 + tid] = m_run[tid];
        g_pixsum[half*NPIX + gp0 + tid] = s_run[tid];
    }
}

// ---------------------------------------------------------------------------
// Pass 2: merge the two half-softmax states per pixel, then
// codes *= exp(m_tile - m_fin)/s_fin. One warp per code, 8 codes per block.
// ---------------------------------------------------------------------------
__global__ __launch_bounds__(256)
void pass2_kernel(float* __restrict__ out) {
    __shared__ __align__(16) float fac[PPB];

    const int b   = blockIdx.x >> 8;          // 256 blocks per batch
    const int k0  = (blockIdx.x & 255) * 8;
    const int tile = k0 >> 8;
    const int tid = threadIdx.x;

    for (int t = tid; t < PPB; t += 256) {
        int pix = b*PPB + t;
        float m0 = g_pixmax[pix],        m1 = g_pixmax[NPIX + pix];
        float s0 = g_pixsum[pix],        s1 = g_pixsum[NPIX + pix];
        float mf = fmaxf(m0, m1);
        float sf = s0*__expf(m0 - mf) + s1*__expf(m1 - mf);
        float mt = g_mtile[tile*NPIX + pix];
        fac[t] = __expf(mt - mf) * __frcp_rn(sf);
    }
    __syncthreads();

    const int w = tid >> 5, lane = tid & 31;
    const int k = k0 + w;
    float4* p = reinterpret_cast<float4*>(out + (size_t)BOWOFF + ((size_t)(b*NK + k))*PPB);
    const float4* f4p = reinterpret_cast<const float4*>(fac);

    float acc = 0.f;
    #pragma unroll 2
    for (int t = lane; t < PPB/4; t += 32) {
        float4 v  = p[t];
        float4 f4 = f4p[t];
        v.x *= f4.x; v.y *= f4.y; v.z *= f4.z; v.w *= f4.w;
        p[t] = v;
        acc += (v.x + v.y) + (v.z + v.w);
    }
    #pragma unroll
    for (int o = 16; o; o >>= 1) acc += __shfl_xor_sync(0xffffffffu, acc, o);
    if (lane == 0) g_bow[b*NK + k] = acc;
}

// ---------------------------------------------------------------------------
// Pass 3: bow normalize
// ---------------------------------------------------------------------------
__global__ __launch_bounds__(256)
void pass3_kernel(float* __restrict__ out) {
    __shared__ float redw[8];
    __shared__ float denom_s;
    int b   = blockIdx.x;
    int tid = threadIdx.x;
    const float invP = 1.0f / (float)PPB;

    float acc = 0.f;
    for (int k = tid; k < NK; k += 256) acc += g_bow[b*NK + k] * invP;
    #pragma unroll
    for (int o = 16; o; o >>= 1) acc += __shfl_xor_sync(0xffffffffu, acc, o);
    if ((tid & 31) == 0) redw[tid >> 5] = acc;
    __syncthreads();
    if (tid == 0) {
        float t = 0.f;
        #pragma unroll
        for (int i = 0; i < 8; i++) t += redw[i];
        denom_s = fmaxf(t, 1e-12f);
    }
    __syncthreads();
    float den = denom_s;
    for (int k = tid; k < NK; k += 256)
        out[b*NK + k] = (g_bow[b*NK + k] * invP) / den;
}

// ---------------------------------------------------------------------------
extern "C" void kernel_launch(void* const* d_in, const int* in_sizes, int n_in,
                              void* d_out, int out_size) {
    const float* feat = (const float*)d_in[0];   // (32,256,30,30)
    const float* emb  = (const float*)d_in[1];   // (2048,256)
    const float* md   = (const float*)d_in[2];   // (1,)
    float* out = (float*)d_out;

    cudaFuncSetAttribute(pass1_kernel,
                         cudaFuncAttributeMaxDynamicSharedMemorySize, SMEM1_BYTES);

    prep_kernel <<<NK/2, 256>>>(emb);
    pass1_kernel<<<(NPIX/BM)*2, 256, SMEM1_BYTES>>>(feat, md, out);
    pass2_kernel<<<BB*NK/8, 256>>>(out);
    pass3_kernel<<<BB, 256>>>(out);
    (void)in_sizes; (void)n_in; (void)out_size;
}